// round 16
// baseline (speedup 1.0000x reference)
#include <cuda_runtime.h>
#include <cstdint>
#include <math.h>

#define LEVELS 3
#define BINS 9
#define NATOMS 51
#define ADIM 6
#define NB 4096
#define SLAB 8262                 // full per-batch floats (162*51)
#define NSIX 6
#define TROWS 27                  // rows per sixth
#define TSLAB 1377                // floats per sixth (27*51)
#define TSLAB_BYTES 5508          // == 4 mod 16
#define SLOT_BYTES 5520           // 16B-multiple slot / bulk-load size
#define V_MIN_C (-10.0f)
#define V_MAX_C (10.0f)
#define DZ_C (0.4f)

#define THREADS 32                // ONE warp per CTA
#define GRID NB                   // CTA = one batch element (6 units)

// dyn smem (16B-aligned base):
//   [0,32)     3 mbarriers @ 0,8,16 (+pad)
//   [32,       +3*5520)  input ring  (slot s at 32 + s*5520, data at +m)
//   [16592,    +2*5520)  output ring (slot s at 16592 + s*5520, data at +m)
#define OFF_MBAR 0
#define OFF_IN   32
#define OFF_OUT  (OFF_IN + 3 * SLOT_BYTES)     // 16592
#define DYN_BYTES (OFF_OUT + 2 * SLOT_BYTES)   // 27632

__global__ __launch_bounds__(THREADS)
void c2f_kernel(const float* __restrict__ q,
                const float* __restrict__ reward,
                const float* __restrict__ discount,
                const float* __restrict__ act,
                const float* __restrict__ support,
                const float* __restrict__ low0,
                const float* __restrict__ high0,
                float* __restrict__ out)
{
    const int b = blockIdx.x;
    const int lane = threadIdx.x;

    extern __shared__ __align__(16) char dyn[];
    const uint32_t smem_base = (uint32_t)__cvta_generic_to_shared(dyn);

    __shared__ __align__(16) float4 stbl[NATOMS];   // (wl, wu, lower_bits, 0)

    // ---- lane0: init 3 mbars, fire first 3 loads (continuous streaming starts) ----
    if (lane == 0) {
        #pragma unroll
        for (int s = 0; s < 3; s++) {
            asm volatile("mbarrier.init.shared.b64 [%0], 1;"
                         :: "r"(smem_base + OFF_MBAR + s * 8) : "memory");
        }
        #pragma unroll
        for (int i = 0; i < 3; i++) {
            const int U = b * NSIX + i;
            const int m = (U & 3) * 4;
            const uint32_t mb = smem_base + OFF_MBAR + i * 8;
            const char* src = reinterpret_cast<const char*>(q) + (size_t)U * TSLAB_BYTES - m;
            asm volatile("mbarrier.arrive.expect_tx.shared.b64 _, [%0], %1;"
                         :: "r"(mb), "r"((uint32_t)SLOT_BYTES) : "memory");
            asm volatile("cp.async.bulk.shared::cta.global.mbarrier::complete_tx::bytes "
                         "[%0], [%1], %2, [%3];"
                         :: "r"(smem_base + OFF_IN + i * SLOT_BYTES), "l"(src),
                            "r"((uint32_t)SLOT_BYTES), "r"(mb) : "memory");
        }
    }

    // ---- projection table (depends only on b; overlaps TMA flight) ----
    for (int jj = lane; jj < NATOMS; jj += 32) {
        const float r = reward[b];
        const float d = discount[b];
        const float z = support[jj];
        float Tz = fminf(fmaxf(r + d * z, V_MIN_C), V_MAX_C);
        float bc = (Tz - V_MIN_C) / DZ_C;
        int lo = (int)floorf(bc);
        int up = (int)ceilf(bc);
        if (up > 0 && lo == up) lo -= 1;              // reference fixup 1
        if (lo < NATOMS - 1 && lo == up) up += 1;     // reference fixup 2 => up==lo+1
        stbl[jj] = make_float4((float)up - bc, bc - (float)lo,
                               __int_as_float(lo), 0.0f);
    }

    // ---- encode + decode (once per batch element; lanes 0..5) ----
    if (lane < ADIM) {
        const int dim = lane;
        const float a = act[b * ADIM + dim];
        float low = low0[dim], high = high0[dim];
        float idx[LEVELS];
        #pragma unroll
        for (int lvl = 0; lvl < LEVELS; lvl++) {
            float sr = (high - low) / (float)BINS;
            float id = floorf((a - low) / sr);
            id = fminf(fmaxf(id, 0.0f), (float)(BINS - 1));
            float na = fminf(fmaxf(low + sr * id, -1.0f), 1.0f);
            low  = fmaxf(-1.0f, na);
            high = fminf(1.0f, na + sr);
            idx[lvl] = id;
        }
        low = low0[dim]; high = high0[dim];
        #pragma unroll
        for (int lvl = 0; lvl < LEVELS; lvl++) {
            float sr = (high - low) / (float)BINS;
            float cont = low + sr * idx[lvl];
            low  = fmaxf(-1.0f, cont);
            high = fminf(1.0f, cont + sr);
        }
        out[(size_t)NB * SLAB + (size_t)b * ADIM + dim] = 0.5f * (high + low);
    }
    __syncwarp();   // mbar inits + table visible within the warp

    // ---- main loop over the 6 units; depth-3 input ring, depth-2 output ring ----
    #pragma unroll 1
    for (int i = 0; i < NSIX; i++) {
        const int U = b * NSIX + i;
        const int m = (U & 3) * 4;
        const int is = i % 3;                  // input slot
        const int os = i & 1;                  // output slot

        // free this output slot: allow only the previous store to stay in flight
        if (lane == 0 && i >= 2) {
            asm volatile("cp.async.bulk.wait_group 1;" ::: "memory");
        }
        __syncwarp();

        // wait for input slot is (parity flips every 3 units)
        {
            const uint32_t mb = smem_base + OFF_MBAR + is * 8;
            const uint32_t ph = (uint32_t)((i / 3) & 1);
            asm volatile(
                "{\n\t"
                ".reg .pred P;\n\t"
                "WAIT_%=:\n\t"
                "mbarrier.try_wait.parity.acquire.cta.shared::cta.b64 P, [%0], %1, 0x989680;\n\t"
                "@!P bra WAIT_%=;\n\t"
                "}"
                :: "r"(mb), "r"(ph) : "memory");
        }

        float* sp = reinterpret_cast<float*>(dyn + OFF_IN  + is * SLOT_BYTES + m);
        float* so = reinterpret_cast<float*>(dyn + OFF_OUT + os * SLOT_BYTES + m);

        // walk: one thread per row, single pass j=0..50, gap zero-fill
        if (lane < TROWS) {
            const float* pr = sp + lane * NATOMS;  // stride 51 (odd) -> conflict-free
            float* po = so + lane * NATOMS;
            int kcur = __float_as_int(stbl[0].z);
            for (int k = 0; k < kcur; k++) po[k] = 0.0f;
            float accA = 0.0f, accB = 0.0f, carryB = 0.0f;
            #pragma unroll 1
            for (int j = 0; j < NATOMS; j++) {
                const float4 tb = stbl[j];         // LDS.128 broadcast
                const int kj = __float_as_int(tb.z);
                if (kj != kcur) {                  // uniform branch
                    po[kcur] = accA + carryB;
                    if (kj == kcur + 1) {
                        carryB = accB;
                    } else {
                        po[kcur + 1] = accB;
                        for (int k = kcur + 2; k < kj; k++) po[k] = 0.0f;
                        carryB = 0.0f;
                    }
                    accA = 0.0f; accB = 0.0f; kcur = kj;
                }
                const float p = pr[j];
                accA = fmaf(p, tb.x, accA);
                accB = fmaf(p, tb.y, accB);
            }
            po[kcur] = accA + carryB;
            po[kcur + 1] = accB;                   // kcur <= 49 -> safe
            for (int k = kcur + 2; k < NATOMS; k++) po[k] = 0.0f;
        }
        __syncwarp();

        // store: head/tail scalar floats + 16B-aligned interior via bulk
        const int h        = ((16 - m) & 15) >> 2;          // head floats (0..3)
        const int rem      = TSLAB_BYTES - h * 4;
        const int interior = rem & ~15;
        const int tailf    = (rem & 15) >> 2;               // tail floats (0..3)
        if (lane < 4) {
            float* dst = out + (size_t)U * TSLAB;
            if (lane < h)     dst[lane] = so[lane];
            if (lane < tailf) dst[TSLAB - 1 - lane] = so[TSLAB - 1 - lane];
        }
        if (lane == 0) {
            asm volatile("fence.proxy.async.shared::cta;" ::: "memory");
            const uint32_t src_s = smem_base
                                 + (uint32_t)(OFF_OUT + os * SLOT_BYTES + m + h * 4);
            char* dst_al = reinterpret_cast<char*>(out) + (size_t)U * TSLAB_BYTES + h * 4;
            asm volatile("cp.async.bulk.global.shared::cta.bulk_group [%0], [%1], %2;"
                         :: "l"(dst_al), "r"(src_s), "r"((uint32_t)interior) : "memory");
            asm volatile("cp.async.bulk.commit_group;" ::: "memory");

            // refill the input ring: fire load for unit i+3
            if (i + 3 < NSIX) {
                const int Un = b * NSIX + i + 3;
                const int mn = (Un & 3) * 4;
                const uint32_t mb = smem_base + OFF_MBAR + ((i + 3) % 3) * 8;
                const char* src = reinterpret_cast<const char*>(q)
                                + (size_t)Un * TSLAB_BYTES - mn;
                asm volatile("mbarrier.arrive.expect_tx.shared.b64 _, [%0], %1;"
                             :: "r"(mb), "r"((uint32_t)SLOT_BYTES) : "memory");
                asm volatile("cp.async.bulk.shared::cta.global.mbarrier::complete_tx::bytes "
                             "[%0], [%1], %2, [%3];"
                             :: "r"(smem_base + OFF_IN + ((i + 3) % 3) * SLOT_BYTES), "l"(src),
                                "r"((uint32_t)SLOT_BYTES), "r"(mb) : "memory");
            }
        }
    }

    // ---- single exposed drain per 6 units ----
    if (lane == 0) {
        asm volatile("cp.async.bulk.wait_group 0;" ::: "memory");
    }
}

extern "C" void kernel_launch(void* const* d_in, const int* in_sizes, int n_in,
                              void* d_out, int out_size)
{
    const float* q        = (const float*)d_in[0];
    const float* reward   = (const float*)d_in[1];
    const float* discount = (const float*)d_in[2];
    const float* act      = (const float*)d_in[3];
    const float* support  = (const float*)d_in[4];
    const float* low0     = (const float*)d_in[5];
    const float* high0    = (const float*)d_in[6];
    float* out = (float*)d_out;

    cudaFuncSetAttribute(c2f_kernel, cudaFuncAttributeMaxDynamicSharedMemorySize,
                         DYN_BYTES);
    c2f_kernel<<<GRID, THREADS, DYN_BYTES>>>(q, reward, discount, act, support,
                                             low0, high0, out);
}

// round 17
// speedup vs baseline: 1.3857x; 1.3857x over previous
#include <cuda_runtime.h>
#include <cstdint>
#include <math.h>

#define LEVELS 3
#define BINS 9
#define NATOMS 51
#define ADIM 6
#define NB 4096
#define SLAB 8262                 // full per-batch floats (162*51)
#define NSIX 6
#define TROWS 27                  // rows per sixth
#define TSLAB 1377                // floats per sixth (27*51)
#define TSLAB_BYTES 5508          // == 4 mod 16
#define LOAD_BYTES 5520           // 16B-rounded staged size
#define NCHUNK (LOAD_BYTES / 16)  // 345 16-byte chunks
#define V_MIN_C (-10.0f)
#define V_MAX_C (10.0f)
#define DZ_C (0.4f)

#define THREADS 64
#define GRID (NB * NSIX)          // 24576

// dyn smem (16B-aligned base):
//   [0, 5520)      input slot  (data at +m)
//   [5520, +5520)  output slot (data at +m)
#define OFF_IN   0
#define OFF_OUT  LOAD_BYTES                 // 5520
#define DYN_BYTES (OFF_OUT + LOAD_BYTES)    // 11040

__global__ __launch_bounds__(THREADS)
void c2f_kernel(const float* __restrict__ q,
                const float* __restrict__ reward,
                const float* __restrict__ discount,
                const float* __restrict__ act,
                const float* __restrict__ support,
                const float* __restrict__ low0,
                const float* __restrict__ high0,
                float* __restrict__ out)
{
    const int U = blockIdx.x;             // sixth index
    const int t = threadIdx.x;
    const int b = U / NSIX;               // batch element
    const int sixth = U - b * NSIX;
    const int m = (U & 3) * 4;            // byte misalignment of U*5508 mod 16

    extern __shared__ __align__(16) char dyn[];
    const uint32_t smem_base = (uint32_t)__cvta_generic_to_shared(dyn);

    float* sp = reinterpret_cast<float*>(dyn + OFF_IN  + m);   // staged probs
    float* so = reinterpret_cast<float*>(dyn + OFF_OUT + m);   // staged result

    __shared__ __align__(16) float4 stbl[NATOMS];   // (wl, wu, lower_bits, 0)

    // ---- stage input via per-thread cp.async.cg (16B chunks, L1-bypass).
    //      Source aligned-down by m; 5520 B covers the unit exactly; the over-
    //      read (<=12 B) stays in-array because the final unit has m == 12.
    {
        const char* src = reinterpret_cast<const char*>(q) + (size_t)U * TSLAB_BYTES - m;
        #pragma unroll
        for (int k = 0; k < 6; k++) {
            const int idx = t + k * THREADS;          // chunk index
            if (idx < NCHUNK) {
                asm volatile("cp.async.cg.shared.global [%0], [%1], 16;"
                             :: "r"(smem_base + OFF_IN + idx * 16),
                                "l"(src + (size_t)idx * 16) : "memory");
            }
        }
        asm volatile("cp.async.commit_group;" ::: "memory");
    }

    // ---- projection table (block-uniform; overlaps the async loads) ----
    if (t < NATOMS) {
        const float r = reward[b];
        const float d = discount[b];
        const float z = support[t];
        float Tz = fminf(fmaxf(r + d * z, V_MIN_C), V_MAX_C);
        float bc = (Tz - V_MIN_C) / DZ_C;
        int lo = (int)floorf(bc);
        int up = (int)ceilf(bc);
        if (up > 0 && lo == up) lo -= 1;              // reference fixup 1
        if (lo < NATOMS - 1 && lo == up) up += 1;     // reference fixup 2 => up==lo+1
        stbl[t] = make_float4((float)up - bc, bc - (float)lo,
                              __int_as_float(lo), 0.0f);
    }

    // ---- encode + decode: only in the sixth==0 CTA of each batch element ----
    if (sixth == 0 && t >= 52 && t < 52 + ADIM) {
        const int dim = t - 52;
        const float a = act[b * ADIM + dim];
        float low = low0[dim], high = high0[dim];
        float idx[LEVELS];
        #pragma unroll
        for (int lvl = 0; lvl < LEVELS; lvl++) {
            float sr = (high - low) / (float)BINS;
            float id = floorf((a - low) / sr);
            id = fminf(fmaxf(id, 0.0f), (float)(BINS - 1));
            float na = fminf(fmaxf(low + sr * id, -1.0f), 1.0f);
            low  = fmaxf(-1.0f, na);
            high = fminf(1.0f, na + sr);
            idx[lvl] = id;
        }
        low = low0[dim]; high = high0[dim];
        #pragma unroll
        for (int lvl = 0; lvl < LEVELS; lvl++) {
            float sr = (high - low) / (float)BINS;
            float cont = low + sr * idx[lvl];
            low  = fmaxf(-1.0f, cont);
            high = fminf(1.0f, cont + sr);
        }
        out[(size_t)NB * SLAB + (size_t)b * ADIM + dim] = 0.5f * (high + low);
    }

    // ---- wait for this CTA's staged input; then make it visible block-wide ----
    asm volatile("cp.async.wait_group 0;" ::: "memory");
    __syncthreads();

    // ---- walk: one thread per row, single pass j=0..50, gap zero-fill ----
    if (t < TROWS) {
        const float* pr = sp + t * NATOMS;   // stride 51 (odd) -> conflict-free
        float* po = so + t * NATOMS;
        int kcur = __float_as_int(stbl[0].z);
        for (int k = 0; k < kcur; k++) po[k] = 0.0f;
        float accA = 0.0f, accB = 0.0f, carryB = 0.0f;
        #pragma unroll 1
        for (int j = 0; j < NATOMS; j++) {
            const float4 tb = stbl[j];       // LDS.128 broadcast
            const int kj = __float_as_int(tb.z);
            if (kj != kcur) {                // uniform branch
                po[kcur] = accA + carryB;
                if (kj == kcur + 1) {
                    carryB = accB;
                } else {
                    po[kcur + 1] = accB;
                    for (int k = kcur + 2; k < kj; k++) po[k] = 0.0f;
                    carryB = 0.0f;
                }
                accA = 0.0f; accB = 0.0f; kcur = kj;
            }
            const float p = pr[j];
            accA = fmaf(p, tb.x, accA);
            accB = fmaf(p, tb.y, accB);
        }
        po[kcur] = accA + carryB;
        po[kcur + 1] = accB;                 // kcur <= 49 -> safe
        for (int k = kcur + 2; k < NATOMS; k++) po[k] = 0.0f;
    }
    __syncthreads();

    // ---- store: head/tail scalar floats + 16B-aligned interior via bulk ----
    const int h        = ((16 - m) & 15) >> 2;          // head floats (0..3)
    const int rem      = TSLAB_BYTES - h * 4;
    const int interior = rem & ~15;
    const int tailf    = (rem & 15) >> 2;               // tail floats (0..3)
    if (t < 4) {
        float* dst = out + (size_t)U * TSLAB;
        if (t < h)     dst[t] = so[t];
        if (t < tailf) dst[TSLAB - 1 - t] = so[TSLAB - 1 - t];
    }
    if (t == 0) {
        asm volatile("fence.proxy.async.shared::cta;" ::: "memory");
        const uint32_t src_s = smem_base + (uint32_t)(OFF_OUT + m + h * 4); // 16B aligned
        char* dst_al = reinterpret_cast<char*>(out) + (size_t)U * TSLAB_BYTES + h * 4;
        asm volatile("cp.async.bulk.global.shared::cta.bulk_group [%0], [%1], %2;"
                     :: "l"(dst_al), "r"(src_s), "r"((uint32_t)interior) : "memory");
        asm volatile("cp.async.bulk.commit_group;" ::: "memory");
        asm volatile("cp.async.bulk.wait_group 0;" ::: "memory");
    }
}

extern "C" void kernel_launch(void* const* d_in, const int* in_sizes, int n_in,
                              void* d_out, int out_size)
{
    const float* q        = (const float*)d_in[0];
    const float* reward   = (const float*)d_in[1];
    const float* discount = (const float*)d_in[2];
    const float* act      = (const float*)d_in[3];
    const float* support  = (const float*)d_in[4];
    const float* low0     = (const float*)d_in[5];
    const float* high0    = (const float*)d_in[6];
    float* out = (float*)d_out;

    cudaFuncSetAttribute(c2f_kernel, cudaFuncAttributeMaxDynamicSharedMemorySize,
                         DYN_BYTES);
    c2f_kernel<<<GRID, THREADS, DYN_BYTES>>>(q, reward, discount, act, support,
                                             low0, high0, out);
}